// round 1
// baseline (speedup 1.0000x reference)
#include <cuda_runtime.h>
#include <cuda_bf16.h>
#include <math.h>
#include <stddef.h>

// ---------------------------------------------------------------------------
// Problem constants
//   x: (8, 256, 64, 64)  HEADS=8 DIM_HEAD=32 INNER=256 FFI=1024 TOP=16x16
// ---------------------------------------------------------------------------
#define BATCH 8
#define DIM 256
#define HH 64
#define WW 64
#define P 4096            // H*W
#define HEADS 8
#define DHEAD 32
#define INNER 256
#define FFI 1024
#define TOPH 16
#define TOPW 16
#define BP 64             // BATCH*HEADS
#define JTOT 256          // TOPH*TOPW

// ---------------------------------------------------------------------------
// Scratch (static device globals; no allocation allowed)
// ---------------------------------------------------------------------------
__device__ float g_xn  [(size_t)BATCH*DIM*P];       // 32MB  LN(x)
__device__ float g_qkv [(size_t)BATCH*768*P];       // 96MB
__device__ float g_attn[(size_t)BATCH*INNER*P];     // 32MB  attention out (pre w_out)
__device__ float g_comb[(size_t)BATCH*512*P];       // 64MB  concat buffer
__device__ float g_ao  [(size_t)BATCH*DIM*P];       // 32MB  attn_out (post comb + residual)
__device__ float g_h   [(size_t)BATCH*FFI*P];       // 128MB
__device__ float g_r   [(size_t)BATCH*FFI*P];       // 128MB
__device__ float g_f2  [(size_t)BATCH*DIM*P];       // 32MB
__device__ float g_kf  [(size_t)BP*JTOT*DHEAD];     // 2MB
__device__ float g_vf  [(size_t)BP*JTOT*DHEAD];     // 2MB

// ---------------------------------------------------------------------------
// Channel LayerNorm over C=256 at each (b, p)
// ---------------------------------------------------------------------------
__global__ void chan_ln_kernel(const float* __restrict__ x,
                               const float* __restrict__ g,
                               const float* __restrict__ bb,
                               float* __restrict__ y)
{
    int idx = blockIdx.x * blockDim.x + threadIdx.x;   // 0..32767
    int b = idx >> 12;
    int p = idx & 4095;
    const float* xb = x + (size_t)b * DIM * P + p;
    float s = 0.f, s2 = 0.f;
    #pragma unroll 8
    for (int c = 0; c < DIM; c++) {
        float v = xb[(size_t)c * P];
        s += v; s2 += v * v;
    }
    float mean = s * (1.f / DIM);
    float var  = s2 * (1.f / DIM) - mean * mean;
    float rstd = rsqrtf(var + 1e-5f);
    float* yb = g_xn + (size_t)b * DIM * P + p;
    (void)y;
    #pragma unroll 8
    for (int c = 0; c < DIM; c++) {
        float v = xb[(size_t)c * P];
        yb[(size_t)c * P] = (v - mean) * rstd * g[c] + bb[c];
    }
}

// ---------------------------------------------------------------------------
// SGEMM: C[M,N] = A[M,K] * B[K,N] (+bias[m]) (+res), batched over z (B,C,res)
// 128x128x16 tile, 256 threads, 8x8 microtile.  M%128==0, K%16==0, N%4==0.
// ---------------------------------------------------------------------------
#define TBM 128
#define TBN 128
#define TBK 16

__global__ void __launch_bounds__(256)
sgemm_kernel(const float* __restrict__ A, const float* __restrict__ B,
             float* __restrict__ C, int M, int N, int K,
             size_t strideB, size_t strideC, size_t strideR,
             const float* __restrict__ bias, const float* __restrict__ res)
{
    __shared__ float As[TBK][TBM + 4];
    __shared__ float Bs[TBK][TBN];

    int bz = blockIdx.z;
    const float* Bp = B + (size_t)bz * strideB;
    float*       Cp = C + (size_t)bz * strideC;
    const float* Rp = res ? res + (size_t)bz * strideR : nullptr;

    int m0 = blockIdx.y * TBM, n0 = blockIdx.x * TBN;
    int t  = threadIdx.x;
    int tx = t & 15, ty = t >> 4;

    float acc[8][8];
    #pragma unroll
    for (int i = 0; i < 8; i++)
        #pragma unroll
        for (int j = 0; j < 8; j++) acc[i][j] = 0.f;

    int arow = t >> 2;          // 0..63
    int akv  = (t & 3) * 4;     // 0,4,8,12
    int brow = t >> 5;          // 0..7
    int bnv  = (t & 31) * 4;    // 0..124

    for (int k0 = 0; k0 < K; k0 += TBK) {
        #pragma unroll
        for (int ps = 0; ps < 2; ps++) {
            int r = arow + ps * 64;
            float4 av = *(const float4*)&A[(size_t)(m0 + r) * K + k0 + akv];
            As[akv + 0][r] = av.x; As[akv + 1][r] = av.y;
            As[akv + 2][r] = av.z; As[akv + 3][r] = av.w;
        }
        #pragma unroll
        for (int ps = 0; ps < 2; ps++) {
            int r = brow + ps * 8;
            float4 bv = *(const float4*)&Bp[(size_t)(k0 + r) * N + n0 + bnv];
            *(float4*)&Bs[r][bnv] = bv;
        }
        __syncthreads();
        #pragma unroll
        for (int kk = 0; kk < TBK; kk++) {
            float4 a0 = *(const float4*)&As[kk][ty * 4];
            float4 a1 = *(const float4*)&As[kk][ty * 4 + 64];
            float4 b0 = *(const float4*)&Bs[kk][tx * 4];
            float4 b1 = *(const float4*)&Bs[kk][tx * 4 + 64];
            float a[8] = {a0.x, a0.y, a0.z, a0.w, a1.x, a1.y, a1.z, a1.w};
            float bv[8] = {b0.x, b0.y, b0.z, b0.w, b1.x, b1.y, b1.z, b1.w};
            #pragma unroll
            for (int i = 0; i < 8; i++)
                #pragma unroll
                for (int j = 0; j < 8; j++)
                    acc[i][j] += a[i] * bv[j];
        }
        __syncthreads();
    }

    #pragma unroll
    for (int ib = 0; ib < 2; ib++) {
        #pragma unroll
        for (int iq = 0; iq < 4; iq++) {
            int i = ib * 4 + iq;
            int m = m0 + ty * 4 + iq + ib * 64;
            float bbv = bias ? bias[m] : 0.f;
            #pragma unroll
            for (int jb = 0; jb < 2; jb++) {
                int n = n0 + tx * 4 + jb * 64;
                size_t off = (size_t)m * N + n;
                float4 o;
                o.x = acc[i][jb * 4 + 0] + bbv;
                o.y = acc[i][jb * 4 + 1] + bbv;
                o.z = acc[i][jb * 4 + 2] + bbv;
                o.w = acc[i][jb * 4 + 3] + bbv;
                if (Rp) {
                    float4 rr = *(const float4*)&Rp[off];
                    o.x += rr.x; o.y += rr.y; o.z += rr.z; o.w += rr.w;
                }
                *(float4*)&Cp[off] = o;
            }
        }
    }
}

// ---------------------------------------------------------------------------
// L2-norm over W (last dim) for q and k sections of qkv (channels 0..511)
// one warp per row of 64
// ---------------------------------------------------------------------------
__global__ void l2norm_kernel(float* __restrict__ qkv)
{
    int r = blockIdx.x * 8 + (threadIdx.x >> 5);   // 0 .. 8*512*64-1
    int lane = threadIdx.x & 31;
    int b   = r >> 15;          // / (512*64)
    int rem = r & 32767;
    int ch  = rem >> 6;         // 0..511
    int h   = rem & 63;
    float* base = qkv + ((size_t)(b * 768 + ch)) * P + h * 64;
    float v0 = base[lane], v1 = base[lane + 32];
    float s = v0 * v0 + v1 * v1;
    #pragma unroll
    for (int o = 16; o > 0; o >>= 1) s += __shfl_xor_sync(0xffffffffu, s, o);
    float inv = 1.f / fmaxf(sqrtf(s), 1e-12f);
    base[lane] = v0 * inv;
    base[lane + 32] = v1 * inv;
}

// ---------------------------------------------------------------------------
// Per batch-head: q_probe, row top-16, col top-16, gather kf/vf [256][32]
// ---------------------------------------------------------------------------
__device__ inline void topk16(const float* sc, int* out)
{
    float v[64];
    for (int i = 0; i < 64; i++) v[i] = sc[i];
    for (int k = 0; k < 16; k++) {
        int bi = 0; float bv = v[0];
        for (int i = 1; i < 64; i++) if (v[i] > bv) { bv = v[i]; bi = i; }
        out[k] = bi; v[bi] = -3.0e38f;
    }
}

__global__ void select_gather_kernel(const float* __restrict__ qkv,
                                     float* __restrict__ kf, float* __restrict__ vf)
{
    int bp = blockIdx.x;           // 0..63
    int b = bp >> 3, head = bp & 7;
    const float* qb = qkv + ((size_t)(b * 768 +       head * 32)) * P;
    const float* kb = qkv + ((size_t)(b * 768 + 256 + head * 32)) * P;
    const float* vb = qkv + ((size_t)(b * 768 + 512 + head * 32)) * P;

    __shared__ float s_qp[32];
    __shared__ float s_kh[2048];
    __shared__ float s_sc[64];
    __shared__ int   s_ih[16];
    __shared__ int   s_iw[16];

    int t = threadIdx.x, lane = t & 31, warp = t >> 5;

    // q_probe[c] = sum over all 4096
    for (int c = warp; c < 32; c += 8) {
        const float* row = qb + (size_t)c * P;
        float s = 0.f;
        for (int i = lane; i < P; i += 32) s += row[i];
        #pragma unroll
        for (int o = 16; o > 0; o >>= 1) s += __shfl_down_sync(0xffffffffu, s, o);
        if (lane == 0) s_qp[c] = s;
    }
    __syncthreads();

    // k_height[c][h]
    for (int idx = t; idx < 2048; idx += 256) {
        int c = idx >> 6, h = idx & 63;
        const float* row = kb + (size_t)c * P + h * 64;
        float s = 0.f;
        #pragma unroll 8
        for (int w = 0; w < 64; w++) s += row[w];
        s_kh[idx] = s;
    }
    __syncthreads();
    if (t < 64) {
        float s = 0.f;
        for (int c = 0; c < 32; c++) s += s_qp[c] * s_kh[c * 64 + t];
        s_sc[t] = s;
    }
    __syncthreads();
    if (t == 0) topk16(s_sc, s_ih);
    __syncthreads();

    // k_width[c][w] over selected h
    for (int idx = t; idx < 2048; idx += 256) {
        int c = idx >> 6, w = idx & 63;
        float s = 0.f;
        #pragma unroll
        for (int j = 0; j < 16; j++) s += kb[(size_t)c * P + s_ih[j] * 64 + w];
        s_kh[idx] = s;
    }
    __syncthreads();
    if (t < 64) {
        float s = 0.f;
        for (int c = 0; c < 32; c++) s += s_qp[c] * s_kh[c * 64 + t];
        s_sc[t] = s;
    }
    __syncthreads();
    if (t == 0) topk16(s_sc, s_iw);
    __syncthreads();

    // gather kf/vf: [j=jh*16+jw][d]
    float* kfb = kf + (size_t)bp * (JTOT * DHEAD);
    float* vfb = vf + (size_t)bp * (JTOT * DHEAD);
    for (int idx = t; idx < JTOT * DHEAD; idx += 256) {
        int j = idx >> 5, d = idx & 31;
        int jh = j >> 4, jw = j & 15;
        size_t off = (size_t)d * P + s_ih[jh] * 64 + s_iw[jw];
        kfb[idx] = kb[off];
        vfb[idx] = vb[off];
    }
}

// ---------------------------------------------------------------------------
// Attention: per (b', p): softmax(q.kf^T) @ vf, kf/vf in shared (64KB)
// ---------------------------------------------------------------------------
__global__ void attn_kernel(const float* __restrict__ qkv,
                            const float* __restrict__ kf,
                            const float* __restrict__ vf,
                            float* __restrict__ out)
{
    extern __shared__ float sm[];
    float* skf = sm;
    float* svf = sm + JTOT * DHEAD;

    int bp = blockIdx.y;
    int b = bp >> 3, head = bp & 7;
    const float4* kfb = (const float4*)(kf + (size_t)bp * (JTOT * DHEAD));
    const float4* vfb = (const float4*)(vf + (size_t)bp * (JTOT * DHEAD));
    for (int i = threadIdx.x; i < (JTOT * DHEAD) / 4; i += blockDim.x) {
        ((float4*)skf)[i] = kfb[i];
        ((float4*)svf)[i] = vfb[i];
    }
    __syncthreads();

    int p = blockIdx.x * blockDim.x + threadIdx.x;   // 0..4095
    const float* qb = qkv + ((size_t)(b * 768 + head * 32)) * P + p;
    float qr[32];
    #pragma unroll
    for (int d = 0; d < 32; d++) qr[d] = qb[(size_t)d * P];

    float m = -1e30f;
    for (int j = 0; j < JTOT; j++) {
        const float* kj = skf + j * 32;
        float s = 0.f;
        #pragma unroll
        for (int d = 0; d < 32; d++) s += qr[d] * kj[d];
        m = fmaxf(m, s);
    }
    float l = 0.f, acc[32];
    #pragma unroll
    for (int d = 0; d < 32; d++) acc[d] = 0.f;
    for (int j = 0; j < JTOT; j++) {
        const float* kj = skf + j * 32;
        const float* vj = svf + j * 32;
        float s = 0.f;
        #pragma unroll
        for (int d = 0; d < 32; d++) s += qr[d] * kj[d];
        float e = __expf(s - m);
        l += e;
        #pragma unroll
        for (int d = 0; d < 32; d++) acc[d] += e * vj[d];
    }
    float inv = 1.f / l;
    float* ob = out + ((size_t)(b * INNER + head * 32)) * P + p;
    #pragma unroll
    for (int d = 0; d < 32; d++) ob[(size_t)d * P] = acc[d] * inv;
}

// ---------------------------------------------------------------------------
// Depthwise 3x3 conv (SAME), one thread per output element
// ---------------------------------------------------------------------------
__global__ void dwconv_kernel(const float* __restrict__ x, const float* __restrict__ w,
                              const float* __restrict__ bias, float* __restrict__ y,
                              int C, size_t ybstride)
{
    size_t idx = (size_t)blockIdx.x * blockDim.x + threadIdx.x;
    size_t total = (size_t)BATCH * C * P;
    if (idx >= total) return;
    int p = (int)(idx & 4095);
    int c = (int)((idx >> 12) % C);
    int b = (int)(idx / ((size_t)C * P));
    int h = p >> 6, ww = p & 63;
    const float* xb = x + ((size_t)b * C + c) * P;
    const float* wc = w + c * 9;
    float s = bias[c];
    #pragma unroll
    for (int dh = -1; dh <= 1; dh++) {
        int hh = h + dh;
        if (hh < 0 || hh > 63) continue;
        #pragma unroll
        for (int dw = -1; dw <= 1; dw++) {
            int cw = ww + dw;
            if (cw < 0 || cw > 63) continue;
            s += xb[hh * 64 + cw] * wc[(dh + 1) * 3 + (dw + 1)];
        }
    }
    y[(size_t)b * ybstride + (size_t)c * P + p] = s;
}

// ---------------------------------------------------------------------------
// InstanceNorm over H*W (+ optional exact GELU, + optional residual add)
// mode 0: y = gelu(norm(x));  mode 1: y = base + gelu(norm(x));  mode 2: y = norm(x)
// ---------------------------------------------------------------------------
__device__ inline float gelu_exact(float v)
{
    return 0.5f * v * (1.0f + erff(v * 0.70710678118654752f));
}

__global__ void instnorm_kernel(const float* __restrict__ x, float* __restrict__ y,
                                const float* __restrict__ base, int mode)
{
    size_t blk = blockIdx.x;
    const float* xp = x + blk * P;
    float* yp = y + blk * P;
    const float* bp = base ? base + blk * P : nullptr;
    __shared__ float rs[256], rs2[256];
    int tid = threadIdx.x;
    float s = 0.f, s2 = 0.f;
    for (int i = tid; i < P; i += 256) {
        float v = xp[i];
        s += v; s2 += v * v;
    }
    rs[tid] = s; rs2[tid] = s2;
    __syncthreads();
    for (int o = 128; o > 0; o >>= 1) {
        if (tid < o) { rs[tid] += rs[tid + o]; rs2[tid] += rs2[tid + o]; }
        __syncthreads();
    }
    float mean = rs[0] * (1.f / P);
    float var  = rs2[0] * (1.f / P) - mean * mean;
    float rstd = rsqrtf(var + 1e-5f);
    for (int i = tid; i < P; i += 256) {
        float v = (xp[i] - mean) * rstd;
        if (mode < 2) v = gelu_exact(v);
        if (mode == 1) v += bp[i];
        yp[i] = v;
    }
}

// ---------------------------------------------------------------------------
// Host launch
// ---------------------------------------------------------------------------
extern "C" void kernel_launch(void* const* d_in, const int* in_sizes, int n_in,
                              void* d_out, int out_size)
{
    const float* x      = (const float*)d_in[0];
    const float* ln_g   = (const float*)d_in[1];
    const float* ln_b   = (const float*)d_in[2];
    const float* w_qkv  = (const float*)d_in[3];
    const float* w_out  = (const float*)d_in[4];
    const float* b_out  = (const float*)d_in[5];
    const float* w_dw   = (const float*)d_in[6];
    const float* b_dw   = (const float*)d_in[7];
    const float* w_comb = (const float*)d_in[8];
    const float* b_comb = (const float*)d_in[9];
    const float* w_ff1  = (const float*)d_in[10];
    const float* b_ff1  = (const float*)d_in[11];
    const float* w_ffdw = (const float*)d_in[12];
    const float* b_ffdw = (const float*)d_in[13];
    const float* w_ff2  = (const float*)d_in[14];
    const float* b_ff2  = (const float*)d_in[15];
    (void)in_sizes; (void)n_in; (void)out_size;

    float *xn, *qkv, *attn, *comb, *ao, *h, *r, *f2, *kf, *vf;
    cudaGetSymbolAddress((void**)&xn,   g_xn);
    cudaGetSymbolAddress((void**)&qkv,  g_qkv);
    cudaGetSymbolAddress((void**)&attn, g_attn);
    cudaGetSymbolAddress((void**)&comb, g_comb);
    cudaGetSymbolAddress((void**)&ao,   g_ao);
    cudaGetSymbolAddress((void**)&h,    g_h);
    cudaGetSymbolAddress((void**)&r,    g_r);
    cudaGetSymbolAddress((void**)&f2,   g_f2);
    cudaGetSymbolAddress((void**)&kf,   g_kf);
    cudaGetSymbolAddress((void**)&vf,   g_vf);

    const size_t sP = (size_t)P;

    // 1. channel LN
    chan_ln_kernel<<<(BATCH * P) / 256, 256>>>(x, ln_g, ln_b, xn);

    // 2. qkv = w_qkv @ xn   (M=768, K=256)
    sgemm_kernel<<<dim3(P / TBN, 768 / TBM, BATCH), 256>>>(
        w_qkv, xn, qkv, 768, P, 256, 256 * sP, 768 * sP, 0, nullptr, nullptr);

    // 3. l2-norm over W for q,k
    l2norm_kernel<<<(BATCH * 512 * 64) / 8, 256>>>(qkv);

    // 4. top-16 row/col selection + gather kf/vf
    select_gather_kernel<<<BP, 256>>>(qkv, kf, vf);

    // 5. attention
    cudaFuncSetAttribute(attn_kernel, cudaFuncAttributeMaxDynamicSharedMemorySize,
                         2 * JTOT * DHEAD * (int)sizeof(float));
    attn_kernel<<<dim3(P / 128, BP), 128, 2 * JTOT * DHEAD * sizeof(float)>>>(
        qkv, kf, vf, attn);

    // 6. combined[:, :256] = w_out @ attn + b_out   (M=256, K=256)
    sgemm_kernel<<<dim3(P / TBN, 256 / TBM, BATCH), 256>>>(
        w_out, attn, comb, 256, P, 256, 256 * sP, 512 * sP, 0, b_out, nullptr);

    // 7. combined[:, 256:512] = dwconv3x3(x)
    dwconv_kernel<<<(BATCH * 256 * P) / 256, 256>>>(
        x, w_dw, b_dw, comb + 256 * sP, 256, 512 * sP);

    // 8. attn_out = w_comb @ combined + b_comb + x   (M=256, K=512)
    sgemm_kernel<<<dim3(P / TBN, 256 / TBM, BATCH), 256>>>(
        w_comb, comb, ao, 256, P, 512, 512 * sP, 256 * sP, 256 * sP, b_comb, x);

    // 9. h = w_ff1 @ attn_out + b_ff1   (M=1024, K=256)
    sgemm_kernel<<<dim3(P / TBN, FFI / TBM, BATCH), 256>>>(
        w_ff1, ao, h, FFI, P, 256, 256 * sP, FFI * sP, 0, b_ff1, nullptr);

    // 10. h = gelu(instnorm(h)) in place
    instnorm_kernel<<<BATCH * FFI, 256>>>(h, h, nullptr, 0);

    // 11. r = dwconv3x3(h) + b_ffdw
    dwconv_kernel<<<(BATCH * FFI * P) / 256, 256>>>(
        h, w_ffdw, b_ffdw, r, FFI, FFI * sP);

    // 12. h = h + gelu(instnorm(r))
    instnorm_kernel<<<BATCH * FFI, 256>>>(r, h, h, 1);

    // 13. f2 = w_ff2 @ h + b_ff2   (M=256, K=1024)
    sgemm_kernel<<<dim3(P / TBN, 256 / TBM, BATCH), 256>>>(
        w_ff2, h, f2, 256, P, 1024, FFI * sP, 256 * sP, 0, b_ff2, nullptr);

    // 14. out = instnorm(f2)
    instnorm_kernel<<<BATCH * DIM, 256>>>(f2, (float*)d_out, nullptr, 2);
}

// round 5
// speedup vs baseline: 1.2497x; 1.2497x over previous
#include <cuda_runtime.h>
#include <cuda_bf16.h>
#include <math.h>
#include <stddef.h>
#include <stdint.h>

// ---------------------------------------------------------------------------
// Problem constants
// ---------------------------------------------------------------------------
#define BATCH 8
#define DIM 256
#define P 4096            // H*W = 64*64
#define HEADS 8
#define DHEAD 32
#define INNER 256
#define FFI 1024
#define BP 64             // BATCH*HEADS
#define JTOT 256          // TOPH*TOPW

// ---------------------------------------------------------------------------
// Scratch (static device globals; no allocation allowed)
// ---------------------------------------------------------------------------
__device__ float g_xn  [(size_t)BATCH*DIM*P];
__device__ float g_qkv [(size_t)BATCH*768*P];
__device__ float g_attn[(size_t)BATCH*INNER*P];
__device__ float g_comb[(size_t)BATCH*512*P];
__device__ float g_ao  [(size_t)BATCH*DIM*P];
__device__ float g_h   [(size_t)BATCH*FFI*P];
__device__ float g_r   [(size_t)BATCH*FFI*P];
__device__ float g_f2  [(size_t)BATCH*DIM*P];
__device__ float g_kf  [(size_t)BP*JTOT*DHEAD];
__device__ float g_vf  [(size_t)BP*JTOT*DHEAD];
// bf16 buffers
__device__ __nv_bfloat16 g_wbf [2752512];                 // weights [m][3K]
__device__ __nv_bfloat16 g_abf [(size_t)BATCH*P*2048];    // acts transposed [b][p][2K]

// ---------------------------------------------------------------------------
// Async-copy helpers (sm_80+ PTX, valid under compute_103 virtual arch)
// ---------------------------------------------------------------------------
__device__ __forceinline__ uint32_t smem_u32(const void* p) {
    uint32_t a;
    asm("{ .reg .u64 t; cvta.to.shared.u64 t, %1; cvt.u32.u64 %0, t; }" : "=r"(a) : "l"(p));
    return a;
}
__device__ __forceinline__ void cp_async16(uint32_t dst, const void* src) {
    asm volatile("cp.async.cg.shared.global [%0], [%1], 16;" :: "r"(dst), "l"(src) : "memory");
}
#define CP_COMMIT() asm volatile("cp.async.commit_group;" ::: "memory")
#define CP_WAIT0()  asm volatile("cp.async.wait_group 0;" ::: "memory")

__device__ __forceinline__ void ldsm_x4(uint32_t* r, uint32_t addr) {
    asm volatile("ldmatrix.sync.aligned.m8n8.x4.shared.b16 {%0,%1,%2,%3}, [%4];"
                 : "=r"(r[0]), "=r"(r[1]), "=r"(r[2]), "=r"(r[3]) : "r"(addr));
}
__device__ __forceinline__ void mma16816(float* c, const uint32_t* a, const uint32_t* b) {
    asm volatile(
        "mma.sync.aligned.m16n8k16.row.col.f32.bf16.bf16.f32 "
        "{%0,%1,%2,%3}, {%4,%5,%6,%7}, {%8,%9}, {%0,%1,%2,%3};"
        : "+f"(c[0]), "+f"(c[1]), "+f"(c[2]), "+f"(c[3])
        : "r"(a[0]), "r"(a[1]), "r"(a[2]), "r"(a[3]), "r"(b[0]), "r"(b[1]));
}

// ---------------------------------------------------------------------------
// Weight split: dst[m][3K] = [Whi | Whi | Wlo]
// ---------------------------------------------------------------------------
__global__ void w_split_kernel(const float* __restrict__ src, __nv_bfloat16* __restrict__ dst,
                               int M, int K)
{
    int i = blockIdx.x * blockDim.x + threadIdx.x;
    if (i >= M * K) return;
    int m = i / K, k = i - m * K;
    float v = src[i];
    __nv_bfloat16 hi = __float2bfloat16_rn(v);
    __nv_bfloat16 lo = __float2bfloat16_rn(v - __bfloat162float(hi));
    size_t row = (size_t)m * (3 * K);
    dst[row + k]         = hi;
    dst[row + K + k]     = hi;
    dst[row + 2 * K + k] = lo;
}

// ---------------------------------------------------------------------------
// Transpose+split acts: src [b][K][4096] f32 -> dst [b][4096][2K] bf16 (hi|lo)
// tile: 32 k x 64 p per block.  Scalar smem stores (260B row stride is only
// 4B-aligned -> float4 STS would trap).  Mapping is bank-conflict-free.
// ---------------------------------------------------------------------------
__global__ void ts_split_kernel(const float* __restrict__ src, __nv_bfloat16* __restrict__ dst,
                                int K)
{
    __shared__ float s[32][65];
    int pt = blockIdx.x, kt = blockIdx.y, b = blockIdx.z;
    int t = threadIdx.x;
    const float4* s4 = (const float4*)(src + ((size_t)b * K + kt * 32) * P) + pt * 16;
    int kr = t >> 3, pq = t & 7;
    float4 v0 = s4[(size_t)kr * (P / 4) + pq];
    float4 v1 = s4[(size_t)kr * (P / 4) + pq + 8];
    s[kr][pq * 4 + 0] = v0.x; s[kr][pq * 4 + 1] = v0.y;
    s[kr][pq * 4 + 2] = v0.z; s[kr][pq * 4 + 3] = v0.w;
    s[kr][32 + pq * 4 + 0] = v1.x; s[kr][32 + pq * 4 + 1] = v1.y;
    s[kr][32 + pq * 4 + 2] = v1.z; s[kr][32 + pq * 4 + 3] = v1.w;
    __syncthreads();

    int pr = t >> 2, ks = t & 3;
    __align__(16) __nv_bfloat16 hi[8];
    __align__(16) __nv_bfloat16 lo[8];
    #pragma unroll
    for (int i = 0; i < 8; i++) {
        float f = s[ks * 8 + i][pr];
        hi[i] = __float2bfloat16_rn(f);
        lo[i] = __float2bfloat16_rn(f - __bfloat162float(hi[i]));
    }
    int p = pt * 64 + pr;
    __nv_bfloat16* dp = dst + ((size_t)b * P + p) * (2 * K) + kt * 32 + ks * 8;
    *(uint4*)dp        = *(uint4*)hi;
    *(uint4*)(dp + K)  = *(uint4*)lo;
}

// ---------------------------------------------------------------------------
// HMMA GEMM: C[M,4096] = A2[M,K3] x B2t (acts [p][K2]), 128x128 CTA tile
// A2 rows [Whi|Whi|Wlo] (K3=3K), B2 rows [Bhi|Blo] (K2=2K).
// stage s = 32-element k chunk: A col s*32; B col (s<S2 ? s : s-S2)*32
// 8 warps, each 32(M) x 64(N); double-buffered cp.async; ldmatrix fragments.
// ---------------------------------------------------------------------------
#define AROWB 80   // 64B data + 16B pad (conflict-free LDSM)

__global__ void __launch_bounds__(256, 1)
tc_gemm_kernel(const __nv_bfloat16* __restrict__ A2,
               const __nv_bfloat16* __restrict__ B2,
               float* __restrict__ C, int K3, int K2,
               size_t strideB2, size_t strideC, size_t strideR,
               const float* __restrict__ bias, const float* __restrict__ res)
{
    __shared__ __align__(16) char sA[2][128 * AROWB];
    __shared__ __align__(16) char sB[2][128 * AROWB];

    const int t = threadIdx.x;
    const int wid = t >> 5, l = t & 31;
    const int n0 = blockIdx.x * 128;
    const int m0 = blockIdx.y * 128;
    const int bz = blockIdx.z;
    const __nv_bfloat16* Bp = B2 + (size_t)bz * strideB2;
    float* Cp = C + (size_t)bz * strideC;
    const float* Rp = res ? res + (size_t)bz * strideR : nullptr;

    const int S  = K3 / 32;        // number of 32-element k stages
    const int S2 = K3 / 48;        // = 2K/32, stages covering [Bhi|Blo]

    const int wrow = wid & 3, wcol = wid >> 2;
    const int wm0 = wrow * 32, wn0 = wcol * 64;

    uint32_t sAu[2], sBu[2];
    sAu[0] = smem_u32(&sA[0][0]); sAu[1] = smem_u32(&sA[1][0]);
    sBu[0] = smem_u32(&sB[0][0]); sBu[1] = smem_u32(&sB[1][0]);

    // per-lane ldmatrix base offsets
    const uint32_t aLane = (uint32_t)((wm0 + (l & 15)) * AROWB + (l >> 4) * 16);
    const uint32_t bLane = (uint32_t)((wn0 + ((l >> 4) & 1) * 8 + (l & 7)) * AROWB
                                      + ((l >> 3) & 1) * 16);

    float acc[2][8][4];
    #pragma unroll
    for (int i = 0; i < 2; i++)
        #pragma unroll
        for (int j = 0; j < 8; j++)
            #pragma unroll
            for (int q = 0; q < 4; q++) acc[i][j][q] = 0.f;

    const int lrow = t >> 2, lseg = t & 3;

    auto load_stage = [&](int s, int buf) {
        #pragma unroll
        for (int i = 0; i < 2; i++) {
            int row = i * 64 + lrow;
            uint32_t dst = sAu[buf] + row * AROWB + lseg * 16;
            const char* src = (const char*)A2
                + ((size_t)(m0 + row) * K3 + s * 32) * 2 + lseg * 16;
            cp_async16(dst, src);
        }
        int kb = (s < S2 ? s : s - S2) * 32;
        #pragma unroll
        for (int i = 0; i < 2; i++) {
            int row = i * 64 + lrow;
            uint32_t dst = sBu[buf] + row * AROWB + lseg * 16;
            const char* src = (const char*)Bp
                + ((size_t)(n0 + row) * K2 + kb) * 2 + lseg * 16;
            cp_async16(dst, src);
        }
        CP_COMMIT();
    };

    load_stage(0, 0);

    for (int s = 0; s < S; s++) {
        int buf = s & 1;
        CP_WAIT0();
        __syncthreads();
        if (s + 1 < S) load_stage(s + 1, buf ^ 1);

        #pragma unroll
        for (int kk = 0; kk < 2; kk++) {
            uint32_t afr[2][4];
            #pragma unroll
            for (int mt = 0; mt < 2; mt++)
                ldsm_x4(afr[mt], sAu[buf] + aLane + mt * (16 * AROWB) + kk * 32);
            #pragma unroll
            for (int jj = 0; jj < 4; jj++) {
                uint32_t bfr[4];
                ldsm_x4(bfr, sBu[buf] + bLane + jj * (16 * AROWB) + kk * 32);
                #pragma unroll
                for (int mt = 0; mt < 2; mt++) {
                    mma16816(acc[mt][2 * jj],     afr[mt], bfr);
                    mma16816(acc[mt][2 * jj + 1], afr[mt], bfr + 2);
                }
            }
        }
        __syncthreads();
    }

    // epilogue: direct stores (+bias, +res)
    int g = l >> 2, tig = l & 3;
    #pragma unroll
    for (int mt = 0; mt < 2; mt++) {
        int m1 = m0 + wm0 + mt * 16 + g;
        int m2 = m1 + 8;
        float bv1 = bias ? bias[m1] : 0.f;
        float bv2 = bias ? bias[m2] : 0.f;
        #pragma unroll
        for (int j = 0; j < 8; j++) {
            int p = n0 + wn0 + j * 8 + 2 * tig;
            size_t o1 = (size_t)m1 * P + p;
            size_t o2 = (size_t)m2 * P + p;
            float2 v1, v2;
            v1.x = acc[mt][j][0] + bv1; v1.y = acc[mt][j][1] + bv1;
            v2.x = acc[mt][j][2] + bv2; v2.y = acc[mt][j][3] + bv2;
            if (Rp) {
                float2 r1 = *(const float2*)&Rp[o1];
                float2 r2 = *(const float2*)&Rp[o2];
                v1.x += r1.x; v1.y += r1.y; v2.x += r2.x; v2.y += r2.y;
            }
            *(float2*)&Cp[o1] = v1;
            *(float2*)&Cp[o2] = v2;
        }
    }
}

// ---------------------------------------------------------------------------
// Channel LayerNorm over C=256 at each (b, p)
// ---------------------------------------------------------------------------
__global__ void chan_ln_kernel(const float* __restrict__ x,
                               const float* __restrict__ g,
                               const float* __restrict__ bb,
                               float* __restrict__ y)
{
    int idx = blockIdx.x * blockDim.x + threadIdx.x;
    int b = idx >> 12;
    int p = idx & 4095;
    const float* xb = x + (size_t)b * DIM * P + p;
    float s = 0.f, s2 = 0.f;
    #pragma unroll 8
    for (int c = 0; c < DIM; c++) {
        float v = xb[(size_t)c * P];
        s += v; s2 += v * v;
    }
    float mean = s * (1.f / DIM);
    float var  = s2 * (1.f / DIM) - mean * mean;
    float rstd = rsqrtf(var + 1e-5f);
    float* yb = y + (size_t)b * DIM * P + p;
    #pragma unroll 8
    for (int c = 0; c < DIM; c++) {
        float v = xb[(size_t)c * P];
        yb[(size_t)c * P] = (v - mean) * rstd * g[c] + bb[c];
    }
}

// ---------------------------------------------------------------------------
// L2-norm over W for q,k channels
// ---------------------------------------------------------------------------
__global__ void l2norm_kernel(float* __restrict__ qkv)
{
    int r = blockIdx.x * 8 + (threadIdx.x >> 5);
    int lane = threadIdx.x & 31;
    int b   = r >> 15;
    int rem = r & 32767;
    int ch  = rem >> 6;
    int h   = rem & 63;
    float* base = qkv + ((size_t)(b * 768 + ch)) * P + h * 64;
    float v0 = base[lane], v1 = base[lane + 32];
    float s = v0 * v0 + v1 * v1;
    #pragma unroll
    for (int o = 16; o > 0; o >>= 1) s += __shfl_xor_sync(0xffffffffu, s, o);
    float inv = 1.f / fmaxf(sqrtf(s), 1e-12f);
    base[lane] = v0 * inv;
    base[lane + 32] = v1 * inv;
}

// ---------------------------------------------------------------------------
// Top-16 row/col selection + gather
// ---------------------------------------------------------------------------
__device__ inline void topk16(const float* sc, int* out)
{
    float v[64];
    for (int i = 0; i < 64; i++) v[i] = sc[i];
    for (int k = 0; k < 16; k++) {
        int bi = 0; float bv = v[0];
        for (int i = 1; i < 64; i++) if (v[i] > bv) { bv = v[i]; bi = i; }
        out[k] = bi; v[bi] = -3.0e38f;
    }
}

__global__ void select_gather_kernel(const float* __restrict__ qkv,
                                     float* __restrict__ kf, float* __restrict__ vf)
{
    int bp = blockIdx.x;
    int b = bp >> 3, head = bp & 7;
    const float* qb = qkv + ((size_t)(b * 768 +       head * 32)) * P;
    const float* kb = qkv + ((size_t)(b * 768 + 256 + head * 32)) * P;
    const float* vb = qkv + ((size_t)(b * 768 + 512 + head * 32)) * P;

    __shared__ float s_qp[32];
    __shared__ float s_kh[2048];
    __shared__ float s_sc[64];
    __shared__ int   s_ih[16];
    __shared__ int   s_iw[16];

    int t = threadIdx.x, lane = t & 31, warp = t >> 5;

    for (int c = warp; c < 32; c += 8) {
        const float* row = qb + (size_t)c * P;
        float s = 0.f;
        for (int i = lane; i < P; i += 32) s += row[i];
        #pragma unroll
        for (int o = 16; o > 0; o >>= 1) s += __shfl_down_sync(0xffffffffu, s, o);
        if (lane == 0) s_qp[c] = s;
    }
    __syncthreads();

    for (int idx = t; idx < 2048; idx += 256) {
        int c = idx >> 6, h = idx & 63;
        const float* row = kb + (size_t)c * P + h * 64;
        float s = 0.f;
        #pragma unroll 8
        for (int w = 0; w < 64; w++) s += row[w];
        s_kh[idx] = s;
    }
    __syncthreads();
    if (t < 64) {
        float s = 0.f;
        for (int c = 0; c < 32; c++) s += s_qp[c] * s_kh[c * 64 + t];
        s_sc[t] = s;
    }
    __syncthreads();
    if (t == 0) topk16(s_sc, s_ih);
    __syncthreads();

    for (int idx = t; idx < 2048; idx += 256) {
        int c = idx >> 6, w = idx & 63;
        float s = 0.f;
        #pragma unroll
        for (int j = 0; j < 16; j++) s += kb[(size_t)c * P + s_ih[j] * 64 + w];
        s_kh[idx] = s;
    }
    __syncthreads();
    if (t < 64) {
        float s = 0.f;
        for (int c = 0; c < 32; c++) s += s_qp[c] * s_kh[c * 64 + t];
        s_sc[t] = s;
    }
    __syncthreads();
    if (t == 0) topk16(s_sc, s_iw);
    __syncthreads();

    float* kfb = kf + (size_t)bp * (JTOT * DHEAD);
    float* vfb = vf + (size_t)bp * (JTOT * DHEAD);
    for (int idx = t; idx < JTOT * DHEAD; idx += 256) {
        int j = idx >> 5, d = idx & 31;
        int jh = j >> 4, jw = j & 15;
        size_t off = (size_t)d * P + s_ih[jh] * 64 + s_iw[jw];
        kfb[idx] = kb[off];
        vfb[idx] = vb[off];
    }
}

// ---------------------------------------------------------------------------
// Attention: single-pass softmax (|q.k| <= 32, rows l2-normalized -> no overflow)
// ---------------------------------------------------------------------------
__global__ void attn_kernel(const float* __restrict__ qkv,
                            const float* __restrict__ kf,
                            const float* __restrict__ vf,
                            float* __restrict__ out)
{
    extern __shared__ float sm[];
    float* skf = sm;
    float* svf = sm + JTOT * DHEAD;

    int bp = blockIdx.y;
    int b = bp >> 3, head = bp & 7;
    const float4* kfb = (const float4*)(kf + (size_t)bp * (JTOT * DHEAD));
    const float4* vfb = (const float4*)(vf + (size_t)bp * (JTOT * DHEAD));
    for (int i = threadIdx.x; i < (JTOT * DHEAD) / 4; i += blockDim.x) {
        ((float4*)skf)[i] = kfb[i];
        ((float4*)svf)[i] = vfb[i];
    }
    __syncthreads();

    int p = blockIdx.x * blockDim.x + threadIdx.x;
    const float* qb = qkv + ((size_t)(b * 768 + head * 32)) * P + p;
    float qr[32];
    #pragma unroll
    for (int d = 0; d < 32; d++) qr[d] = qb[(size_t)d * P];

    float lsum = 0.f, acc[32];
    #pragma unroll
    for (int d = 0; d < 32; d++) acc[d] = 0.f;
    for (int j = 0; j < JTOT; j++) {
        const float* kj = skf + j * 32;
        const float* vj = svf + j * 32;
        float s = 0.f;
        #pragma unroll
        for (int d = 0; d < 32; d++) s += qr[d] * kj[d];
        float e = __expf(s);
        lsum += e;
        #pragma unroll
        for (int d = 0; d < 32; d++) acc[d] += e * vj[d];
    }
    float inv = 1.f / lsum;
    float* ob = out + ((size_t)(b * INNER + head * 32)) * P + p;
    #pragma unroll
    for (int d = 0; d < 32; d++) ob[(size_t)d * P] = acc[d] * inv;
}

// ---------------------------------------------------------------------------
// Depthwise 3x3 conv (SAME)
// ---------------------------------------------------------------------------
__global__ void dwconv_kernel(const float* __restrict__ x, const float* __restrict__ w,
                              const float* __restrict__ bias, float* __restrict__ y,
                              int C, size_t ybstride)
{
    size_t idx = (size_t)blockIdx.x * blockDim.x + threadIdx.x;
    size_t total = (size_t)BATCH * C * P;
    if (idx >= total) return;
    int p = (int)(idx & 4095);
    int c = (int)((idx >> 12) % C);
    int b = (int)(idx / ((size_t)C * P));
    int h = p >> 6, ww = p & 63;
    const float* xb = x + ((size_t)b * C + c) * P;
    const float* wc = w + c * 9;
    float s = bias[c];
    #pragma unroll
    for (int dh = -1; dh <= 1; dh++) {
        int hh = h + dh;
        if (hh < 0 || hh > 63) continue;
        #pragma unroll
        for (int dw = -1; dw <= 1; dw++) {
            int cw = ww + dw;
            if (cw < 0 || cw > 63) continue;
            s += xb[hh * 64 + cw] * wc[(dh + 1) * 3 + (dw + 1)];
        }
    }
    y[(size_t)b * ybstride + (size_t)c * P + p] = s;
}

// ---------------------------------------------------------------------------
// InstanceNorm over H*W (+gelu/+residual)
// ---------------------------------------------------------------------------
__device__ inline float gelu_exact(float v)
{
    return 0.5f * v * (1.0f + erff(v * 0.70710678118654752f));
}

__global__ void instnorm_kernel(const float* __restrict__ x, float* __restrict__ y,
                                const float* __restrict__ base, int mode)
{
    size_t blk = blockIdx.x;
    const float* xp = x + blk * P;
    float* yp = y + blk * P;
    const float* bp = base ? base + blk * P : nullptr;
    __shared__ float rs[256], rs2[256];
    int tid = threadIdx.x;
    float s = 0.f, s2 = 0.f;
    for (int i = tid; i < P; i += 256) {
        float v = xp[i];
        s += v; s2 += v * v;
    }
    rs[tid] = s; rs2[tid] = s2;
    __syncthreads();
    for (int o = 128; o > 0; o >>= 1) {
        if (tid < o) { rs[tid] += rs[tid + o]; rs2[tid] += rs2[tid + o]; }
        __syncthreads();
    }
    float mean = rs[0] * (1.f / P);
    float var  = rs2[0] * (1.f / P) - mean * mean;
    float rstd = rsqrtf(var + 1e-5f);
    for (int i = tid; i < P; i += 256) {
        float v = (xp[i] - mean) * rstd;
        if (mode < 2) v = gelu_exact(v);
        if (mode == 1) v += bp[i];
        yp[i] = v;
    }
}

// ---------------------------------------------------------------------------
// Host launch
// ---------------------------------------------------------------------------
extern "C" void kernel_launch(void* const* d_in, const int* in_sizes, int n_in,
                              void* d_out, int out_size)
{
    const float* x      = (const float*)d_in[0];
    const float* ln_g   = (const float*)d_in[1];
    const float* ln_b   = (const float*)d_in[2];
    const float* w_qkv  = (const float*)d_in[3];
    const float* w_out  = (const float*)d_in[4];
    const float* b_out  = (const float*)d_in[5];
    const float* w_dw   = (const float*)d_in[6];
    const float* b_dw   = (const float*)d_in[7];
    const float* w_comb = (const float*)d_in[8];
    const float* b_comb = (const float*)d_in[9];
    const float* w_ff1  = (const float*)d_in[10];
    const float* b_ff1  = (const float*)d_in[11];
    const float* w_ffdw = (const float*)d_in[12];
    const float* b_ffdw = (const float*)d_in[13];
    const float* w_ff2  = (const float*)d_in[14];
    const float* b_ff2  = (const float*)d_in[15];
    (void)in_sizes; (void)n_in; (void)out_size;

    float *xn, *qkv, *attn, *comb, *ao, *h, *r, *f2, *kf, *vf;
    __nv_bfloat16 *wbf, *abf;
    cudaGetSymbolAddress((void**)&xn,   g_xn);
    cudaGetSymbolAddress((void**)&qkv,  g_qkv);
    cudaGetSymbolAddress((void**)&attn, g_attn);
    cudaGetSymbolAddress((void**)&comb, g_comb);
    cudaGetSymbolAddress((void**)&ao,   g_ao);
    cudaGetSymbolAddress((void**)&h,    g_h);
    cudaGetSymbolAddress((void**)&r,    g_r);
    cudaGetSymbolAddress((void**)&f2,   g_f2);
    cudaGetSymbolAddress((void**)&kf,   g_kf);
    cudaGetSymbolAddress((void**)&vf,   g_vf);
    cudaGetSymbolAddress((void**)&wbf,  g_wbf);
    cudaGetSymbolAddress((void**)&abf,  g_abf);

    const size_t sP = (size_t)P;
    cudaFuncSetAttribute(attn_kernel, cudaFuncAttributeMaxDynamicSharedMemorySize,
                         2 * JTOT * DHEAD * (int)sizeof(float));

    // weight offsets in g_wbf
    const size_t o_qkv  = 0;
    const size_t o_wout = o_qkv  + (size_t)768 * 768;
    const size_t o_comb = o_wout + (size_t)256 * 768;
    const size_t o_ff1  = o_comb + (size_t)256 * 1536;
    const size_t o_ff2  = o_ff1  + (size_t)1024 * 768;

    w_split_kernel<<<(768 * 256 + 255) / 256, 256>>>(w_qkv,  wbf + o_qkv,  768,  256);
    w_split_kernel<<<(256 * 256 + 255) / 256, 256>>>(w_out,  wbf + o_wout, 256,  256);
    w_split_kernel<<<(256 * 512 + 255) / 256, 256>>>(w_comb, wbf + o_comb, 256,  512);
    w_split_kernel<<<(1024 * 256 + 255) / 256, 256>>>(w_ff1, wbf + o_ff1,  1024, 256);
    w_split_kernel<<<(256 * 1024 + 255) / 256, 256>>>(w_ff2, wbf + o_ff2,  256,  1024);

    // 1. channel LN
    chan_ln_kernel<<<(BATCH * P) / 256, 256>>>(x, ln_g, ln_b, xn);

    // 2. qkv = w_qkv @ xn
    ts_split_kernel<<<dim3(64, 8, BATCH), 256>>>(xn, abf, 256);
    tc_gemm_kernel<<<dim3(32, 6, BATCH), 256>>>(
        wbf + o_qkv, abf, qkv, 768, 512, sP * 512, 768 * sP, 0, nullptr, nullptr);

    // 3-5. l2norm, selection, attention
    l2norm_kernel<<<(BATCH * 512 * 64) / 8, 256>>>(qkv);
    select_gather_kernel<<<BP, 256>>>(qkv, kf, vf);
    attn_kernel<<<dim3(P / 128, BP), 128, 2 * JTOT * DHEAD * sizeof(float)>>>(
        qkv, kf, vf, attn);

    // 6. comb[:, :256] = w_out @ attn + b_out
    ts_split_kernel<<<dim3(64, 8, BATCH), 256>>>(attn, abf, 256);
    tc_gemm_kernel<<<dim3(32, 2, BATCH), 256>>>(
        wbf + o_wout, abf, comb, 768, 512, sP * 512, 512 * sP, 0, b_out, nullptr);

    // 7. comb[:, 256:512] = dwconv3x3(x)
    dwconv_kernel<<<(BATCH * 256 * P) / 256, 256>>>(
        x, w_dw, b_dw, comb + 256 * sP, 256, 512 * sP);

    // 8. ao = w_comb @ comb + b_comb + x
    ts_split_kernel<<<dim3(64, 16, BATCH), 256>>>(comb, abf, 512);
    tc_gemm_kernel<<<dim3(32, 2, BATCH), 256>>>(
        wbf + o_comb, abf, ao, 1536, 1024, sP * 1024, 256 * sP, 256 * sP, b_comb, x);

    // 9. h = w_ff1 @ ao + b_ff1
    ts_split_kernel<<<dim3(64, 8, BATCH), 256>>>(ao, abf, 256);
    tc_gemm_kernel<<<dim3(32, 8, BATCH), 256>>>(
        wbf + o_ff1, abf, h, 768, 512, sP * 512, 1024 * sP, 0, b_ff1, nullptr);

    // 10-12. gelu(instnorm); dwconv; h += gelu(instnorm(r))
    instnorm_kernel<<<BATCH * FFI, 256>>>(h, h, nullptr, 0);
    dwconv_kernel<<<(BATCH * FFI * P) / 256, 256>>>(h, w_ffdw, b_ffdw, r, FFI, FFI * sP);
    instnorm_kernel<<<BATCH * FFI, 256>>>(r, h, h, 1);

    // 13. f2 = w_ff2 @ h + b_ff2
    ts_split_kernel<<<dim3(64, 32, BATCH), 256>>>(h, abf, 1024);
    tc_gemm_kernel<<<dim3(32, 2, BATCH), 256>>>(
        wbf + o_ff2, abf, f2, 3072, 2048, sP * 2048, 256 * sP, 0, b_ff2, nullptr);

    // 14. out = instnorm(f2)
    instnorm_kernel<<<BATCH * DIM, 256>>>(f2, (float*)d_out, nullptr, 2);
}